// round 8
// baseline (speedup 1.0000x reference)
#include <cuda_runtime.h>
#include <cuda_fp16.h>
#include <math.h>

#define BB 4
#define CC 8
#define HH 192
#define WW 256
#define HWP (HH*WW)
#define CHW (CC*HWP)
#define NPB 192            // blocks per batch (128 thr x 2 px = 256 px/block)
#define GW 0.01f

// packed pixel-major scratch (built once per launch)
__device__ __align__(16) __half g_I0h[(size_t)BB*HWP*8];   // [b][i][c]
__device__ __align__(16) __half g_I1h[(size_t)BB*HWP*8];   // [b][i][c]
__device__ __align__(16) __half g_Gh [(size_t)BB*HWP*16];  // [b][i][(gx,gy) per c]
__device__ __align__(8) __half g_Nh[(size_t)BB*HWP*4];     // normal half4
__device__ float  g_d0[(size_t)BB*HWP];                    // depth0 (V reconstructed)
__device__ float  g_d1[(size_t)BB*HWP];
__device__ float  g_pose[BB*16];
__device__ double g_part[(size_t)BB*NPB*27];

// ---------------------------------------------------------------------------
__global__ void precompute_kernel(const float* __restrict__ pose,
                                  const float* __restrict__ I0,
                                  const float* __restrict__ I1,
                                  const float* __restrict__ depth0,
                                  const float* __restrict__ depth1,
                                  const float* __restrict__ intr)
{
    int p = blockIdx.x * blockDim.x + threadIdx.x;
    if (p < BB*16) g_pose[p] = pose[p];
    if (p >= BB*HWP) return;
    int b = p / HWP;
    int i = p - b*HWP;
    int h = i / WW, w = i - h*WW;
    float fx = intr[b*4+0], fy = intr[b*4+1], cx = intr[b*4+2], cy = intr[b*4+3];
    int wl = max(w-1, 0), wr = min(w+1, WW-1);
    int hu = max(h-1, 0), hd = min(h+1, HH-1);

    const float* d0 = depth0 + b*HWP;
    float dc = d0[i];
    g_d0[p] = dc;
    g_d1[p] = depth1[p];

    float dl = d0[h*WW+wl], dr = d0[h*WW+wr];
    float du_ = d0[hu*WW+w], dd = d0[hd*WW+w];
    float pxc = ((float)w - cx)/fx, pyc = ((float)h - cy)/fy;
    float pxl = ((float)wl - cx)/fx, pxr = ((float)wr - cx)/fx;
    float pyu = ((float)hu - cy)/fy, pyd = ((float)hd - cy)/fy;
    float dx0 = 0.5f*(pxr*dr - pxl*dl);
    float dx1 = 0.5f*(pyc*dr - pyc*dl);
    float dx2 = 0.5f*(dr - dl);
    float dy0 = 0.5f*(pxc*dd - pxc*du_);
    float dy1 = 0.5f*(pyd*dd - pyu*du_);
    float dy2 = 0.5f*(dd - du_);
    float nx = dx1*dy2 - dx2*dy1;
    float ny = dx2*dy0 - dx0*dy2;
    float nz = dx0*dy1 - dx1*dy0;
    float inv = 1.0f / sqrtf(nx*nx + ny*ny + nz*nz + 1e-12f);
    {
        __half2 n01 = __floats2half2_rn(nx*inv, ny*inv);
        __half2 n23 = __floats2half2_rn(nz*inv, 0.f);
        uint2 nq;
        nq.x = *(unsigned*)&n01;
        nq.y = *(unsigned*)&n23;
        *(uint2*)(g_Nh + (size_t)p*4) = nq;
    }

    float i0v[8], i1v[8], gxy[16];
    #pragma unroll
    for (int c = 0; c < CC; c++) {
        const float* F = I0 + b*CHW + c*HWP;
        i0v[c] = F[i];
        i1v[c] = I1[b*CHW + c*HWP + i];
        gxy[2*c  ] = 0.5f*(F[h*WW+wr] - F[h*WW+wl]);
        gxy[2*c+1] = 0.5f*(F[hd*WW+w] - F[hu*WW+w]);
    }
    uint4 q;
    __half2 hh;
    #define PACKH(dst, src) \
        hh = __floats2half2_rn(src[0], src[1]); q.x = *(unsigned*)&hh; \
        hh = __floats2half2_rn(src[2], src[3]); q.y = *(unsigned*)&hh; \
        hh = __floats2half2_rn(src[4], src[5]); q.z = *(unsigned*)&hh; \
        hh = __floats2half2_rn(src[6], src[7]); q.w = *(unsigned*)&hh; \
        *(uint4*)(dst) = q;
    PACKH(g_I0h + (size_t)p*8, i0v)
    PACKH(g_I1h + (size_t)p*8, i1v)
    PACKH(g_Gh  + (size_t)p*16, gxy)
    PACKH(g_Gh  + (size_t)p*16 + 8, (gxy+8))
    #undef PACKH
}

// ---------------------------------------------------------------------------
__global__ __launch_bounds__(128, 6) void reduce_kernel(const float* __restrict__ intr)
{
    int b = blockIdx.y;
    float fx = intr[b*4+0], fy = intr[b*4+1], cx = intr[b*4+2], cy = intr[b*4+3];
    float rfx = 1.f/fx, rfy = 1.f/fy;
    const float* P = g_pose + b*16;
    float R00=P[0], R01=P[1], R02=P[2],  t0=P[3];
    float R10=P[4], R11=P[5], R12=P[6],  t1=P[7];
    float R20=P[8], R21=P[9], R22=P[10], t2=P[11];

    float vals[32];
    #pragma unroll
    for (int k = 0; k < 32; k++) vals[k] = 0.f;

    int ibase = blockIdx.x*256 + threadIdx.x;

    // ---- stage 1: both pixels' headers (overlapped dependent chains) ----
    float d1A = g_d1[(size_t)b*HWP + ibase];
    float d1B = g_d1[(size_t)b*HWP + ibase + 128];

    float wsP[2][4];
    int   o00P[2];
    float XxP[2], XyP[2], XzP[2], d1P[2];

    #pragma unroll
    for (int pp = 0; pp < 2; pp++) {
        int i = ibase + pp*128;
        float d1 = (pp == 0) ? d1A : d1B;
        int h = i >> 8, w = i & 255;           // WW = 256
        float px = ((float)w - cx)*rfx, py = ((float)h - cy)*rfy;
        float v1x = px*d1, v1y = py*d1;
        float Xx = R00*v1x + R01*v1y + R02*d1 + t0;
        float Xy = R10*v1x + R11*v1y + R12*d1 + t1;
        float Xz = R20*v1x + R21*v1y + R22*d1 + t2;
        bool valid = (Xz > 1e-8f);
        float zs = valid ? Xz : 1.f;
        float iz = __fdividef(1.f, zs);
        float u = fx*Xx*iz + cx;
        float v = fy*Xy*iz + cy;
        valid = valid & (u > 0.f) & (u < (float)(WW-1)) & (v > 0.f) & (v < (float)(HH-1));
        float u0f = floorf(u), v0f = floorf(v);
        float du = u - u0f, dv = v - v0f;
        float m = valid ? 1.f : 0.f;
        wsP[pp][0] = m*(1.f-du)*(1.f-dv);
        wsP[pp][1] = m*du*(1.f-dv);
        wsP[pp][2] = m*(1.f-du)*dv;
        wsP[pp][3] = m*du*dv;
        o00P[pp] = valid ? ((int)v0f*WW + (int)u0f) : 0;
        XxP[pp]=Xx; XyP[pp]=Xy; XzP[pp]=zs; d1P[pp]=d1;
    }

    // ---- stage 2: taps + accumulate per pixel (branch-free) ----
    #pragma unroll
    for (int pp = 0; pp < 2; pp++) {
        int i = ibase + pp*128;
        int o00 = o00P[pp];
        int offs[4] = { o00, o00+1, o00+WW, o00+WW+1 };
        float Xx=XxP[pp], Xy=XyP[pp], Xz=XzP[pp];
        float d1 = d1P[pp];
        float v1x = (((float)(i & 255)) - cx)*rfx*d1;
        float v1y = (((float)(i >> 8))  - cy)*rfy*d1;
        float v1z = d1;

        __half2 i0a[4], ga[8], na[2];
        __half2 hz = __float2half2_rn(0.f);
        #pragma unroll
        for (int c = 0; c < 4; c++) i0a[c] = hz;
        #pragma unroll
        for (int c = 0; c < 8; c++) ga[c] = hz;
        na[0] = hz; na[1] = hz;
        float S=0.f, Sx=0.f, Sy=0.f;   // depth0 tap sums for V reconstruction

        #pragma unroll
        for (int t = 0; t < 4; t++) {
            size_t base = (size_t)b*HWP + offs[t];
            float wtf = wsP[pp][t];
            __half2 wt2 = __float2half2_rn(wtf);
            uint4 qI = *(const uint4*)(g_I0h + base*8);
            i0a[0] = __hfma2(wt2, *(__half2*)&qI.x, i0a[0]);
            i0a[1] = __hfma2(wt2, *(__half2*)&qI.y, i0a[1]);
            i0a[2] = __hfma2(wt2, *(__half2*)&qI.z, i0a[2]);
            i0a[3] = __hfma2(wt2, *(__half2*)&qI.w, i0a[3]);
            uint4 qG0 = *(const uint4*)(g_Gh + base*16);
            uint4 qG1 = *(const uint4*)(g_Gh + base*16 + 8);
            ga[0] = __hfma2(wt2, *(__half2*)&qG0.x, ga[0]);
            ga[1] = __hfma2(wt2, *(__half2*)&qG0.y, ga[1]);
            ga[2] = __hfma2(wt2, *(__half2*)&qG0.z, ga[2]);
            ga[3] = __hfma2(wt2, *(__half2*)&qG0.w, ga[3]);
            ga[4] = __hfma2(wt2, *(__half2*)&qG1.x, ga[4]);
            ga[5] = __hfma2(wt2, *(__half2*)&qG1.y, ga[5]);
            ga[6] = __hfma2(wt2, *(__half2*)&qG1.z, ga[6]);
            ga[7] = __hfma2(wt2, *(__half2*)&qG1.w, ga[7]);
            uint2 nq = *(const uint2*)(g_Nh + base*4);
            na[0] = __hfma2(wt2, *(__half2*)&nq.x, na[0]);
            na[1] = __hfma2(wt2, *(__half2*)&nq.y, na[1]);
            float dt = g_d0[base];
            float wd = wtf*dt;
            S += wd;
            if (t == 1 || t == 3) Sx += wd;   // right column (u0+1)
            if (t == 2 || t == 3) Sy += wd;   // bottom row  (v0+1)
        }
        float2 nf01 = __half22float2(na[0]);
        float2 nf2  = __half22float2(na[1]);
        float Nw0 = nf01.x, Nw1 = nf01.y, Nw2 = nf2.x;
        // reconstruct bilinear V0: rV = ( rfx*((u0-cx)S + Sx), rfy*((v0-cy)S + Sy), S )
        float u0c = (float)(o00 & 255) - cx;
        float v0c = (float)(o00 >> 8)  - cy;
        float rVx = rfx*(u0c*S + Sx);
        float rVy = rfy*(v0c*S + Sy);

        float invz = __fdividef(1.f, Xz);
        float a0 = fx*invz, a2 = -fx*Xx*invz*invz;
        float b1 = fy*invz, b2 = -fy*Xy*invz*invz;
        float Jw0[6] = { a2*Xy, a0*Xz - a2*Xx, -a0*Xy, a0, 0.f, a2 };
        float Jw1[6] = { b2*Xy - b1*Xz, -b2*Xx, b1*Xx, 0.f, b1, b2 };

        // photometric factored scalars (zero when invalid: all taps zero)
        float aS=0.f, bS=0.f, cS=0.f, rxS=0.f, ryS=0.f;
        {
            const uint4 qI1 = *(const uint4*)(g_I1h + ((size_t)b*HWP + i)*8);
            const __half2* I1h2 = (const __half2*)&qI1;
            #pragma unroll
            for (int c2 = 0; c2 < 4; c2++) {
                float2 i1f = __half22float2(I1h2[c2]);
                float2 i0f = __half22float2(i0a[c2]);
                float2 g0f = __half22float2(ga[2*c2]);
                float2 g1f = __half22float2(ga[2*c2+1]);
                float rA = i1f.x - i0f.x;
                float rB = i1f.y - i0f.y;
                float wtA = fminf(1.f, __fdividef(0.5f, fabsf(rA)));
                float wtB = fminf(1.f, __fdividef(0.5f, fabsf(rB)));
                aS  += wtA*g0f.x*g0f.x;  bS  += wtA*g0f.x*g0f.y;  cS  += wtA*g0f.y*g0f.y;
                float wrA = wtA*rA;
                rxS += g0f.x*wrA;        ryS += g0f.y*wrA;
                aS  += wtB*g1f.x*g1f.x;  bS  += wtB*g1f.x*g1f.y;  cS  += wtB*g1f.y*g1f.y;
                float wrB = wtB*rB;
                rxS += g1f.x*wrB;        ryS += g1f.y*wrB;
            }
        }

        // ICP point-to-plane row (Nw=S=0 when invalid -> q=0 -> Jz=0)
        float dfx = Xx - rVx, dfy = Xy - rVy, dfz = Xz - S;
        float d2 = dfx*dfx + dfy*dfy + dfz*dfz;
        float q0 = Nw0*R00 + Nw1*R10 + Nw2*R20;
        float q1 = Nw0*R01 + Nw1*R11 + Nw2*R21;
        float q2 = Nw0*R02 + Nw1*R12 + Nw2*R22;
        float Jr0 = q1*v1z - q2*v1y;
        float Jr1 = q2*v1x - q0*v1z;
        float Jr2 = q0*v1y - q1*v1x;
        float sd01 = (d1 / 525.0f) * 5.5f;
        float sd2  = d1*d1*0.4f / (525.0f*1.2f);
        float cov = (q0*q0 + q1*q1)*sd01*sd01 + q2*q2*sd2*sd2;
        float sinv = __frsqrt_rn(cov + 1e-8f);
        float res = (Nw0*dfx + Nw1*dfy + Nw2*dfz) * sinv;
        if (d2 + 1e-12f > 0.01f) res = 1e-6f;
        float Jz[6] = { -Jr0*sinv*GW, -Jr1*sinv*GW, -Jr2*sinv*GW,
                         q0*sinv*GW,   q1*sinv*GW,   q2*sinv*GW };
        float rz = -GW * res;
        float wz = fminf(1.f, __fdividef(0.5f, fabsf(rz)));
        float wrz = wz * rz;

        float Ai[6], Bi[6], Wi[6];
        #pragma unroll
        for (int ii = 0; ii < 6; ii++) {
            Ai[ii] = aS*Jw0[ii] + bS*Jw1[ii];
            Bi[ii] = bS*Jw0[ii] + cS*Jw1[ii];
            Wi[ii] = wz*Jz[ii];
        }
        int k = 0;
        #pragma unroll
        for (int ii = 0; ii < 6; ii++) {
            #pragma unroll
            for (int jj = ii; jj < 6; jj++)
                vals[k++] += Ai[ii]*Jw0[jj] + Bi[ii]*Jw1[jj] + Wi[ii]*Jz[jj];
            vals[21+ii] += rxS*Jw0[ii] + ryS*Jw1[ii] + Jz[ii]*wrz;
        }
    }

    // ---- butterfly multi-value warp reduction: 31 SHFL total ----
    // After: lane l holds the warp sum of vals[l] (l < 27 meaningful).
    int lane = threadIdx.x & 31, wid = threadIdx.x >> 5;
    #pragma unroll
    for (int off = 16; off >= 1; off >>= 1) {
        bool hi = (lane & off) != 0;
        #pragma unroll
        for (int j = 0; j < off; j++) {
            float send = hi ? vals[j] : vals[j+off];
            float recv = __shfl_xor_sync(0xffffffffu, send, off);
            vals[j] = (hi ? vals[j+off] : vals[j]) + recv;
        }
    }
    __shared__ float sw[4][32];
    sw[wid][lane] = vals[0];
    __syncthreads();
    if (threadIdx.x < 27) {
        double s = 0.0;
        #pragma unroll
        for (int w2 = 0; w2 < 4; w2++) s += (double)sw[w2][threadIdx.x];
        g_part[((size_t)b*NPB + blockIdx.x)*27 + threadIdx.x] = s;
    }
}

// ---------------------------------------------------------------------------
__global__ void solve_kernel(float* __restrict__ out)
{
    int b = blockIdx.x;
    __shared__ float sv[27];
    int t = threadIdx.x;
    int g = t >> 3, l = t & 7;
    bool live = (g < 27);
    double s = 0.0;
    if (live) {
        #pragma unroll 4
        for (int k = l; k < NPB; k += 8)
            s += g_part[((size_t)b*NPB + k)*27 + g];
    }
    #pragma unroll
    for (int off = 4; off > 0; off >>= 1)
        s += __shfl_down_sync(0xffffffffu, s, off, 8);
    if (live && l == 0) sv[g] = (float)s;
    __syncthreads();
    if (t != 0) return;

    float Hm[6][7];
    {
        int k = 0;
        for (int i = 0; i < 6; i++)
            for (int j = i; j < 6; j++) { Hm[i][j] = sv[k]; Hm[j][i] = sv[k]; k++; }
        for (int i = 0; i < 6; i++) Hm[i][i] += 1e-6f;
        for (int i = 0; i < 6; i++) Hm[i][6] = sv[21 + i];
    }
    #pragma unroll
    for (int col = 0; col < 6; col++) {
        int piv = col; float mx = fabsf(Hm[col][col]);
        #pragma unroll
        for (int r = col+1; r < 6; r++)
            if (fabsf(Hm[r][col]) > mx) { mx = fabsf(Hm[r][col]); piv = r; }
        if (piv != col)
            #pragma unroll
            for (int c = 0; c < 7; c++) { float tmp = Hm[col][c]; Hm[col][c] = Hm[piv][c]; Hm[piv][c] = tmp; }
        float inv = 1.0f / Hm[col][col];
        #pragma unroll
        for (int r = col+1; r < 6; r++) {
            float f = Hm[r][col] * inv;
            #pragma unroll
            for (int c = col; c < 7; c++) Hm[r][c] -= f * Hm[col][c];
        }
    }
    float xi[6];
    #pragma unroll
    for (int r = 5; r >= 0; r--) {
        float s2 = Hm[r][6];
        #pragma unroll
        for (int c = r+1; c < 6; c++) s2 -= Hm[r][c] * xi[c];
        xi[r] = s2 / Hm[r][r];
    }
    float wx = xi[0], wy = xi[1], wz = xi[2], vx = xi[3], vy = xi[4], vz = xi[5];
    float th2 = wx*wx + wy*wy + wz*wz;
    float A, Bc, Cc;
    if (th2 < 1e-8f) { A = 1.0f - th2/6.0f; Bc = 0.5f - th2/24.0f; Cc = 1.0f/6.0f - th2/120.0f; }
    else {
        float th = sqrtf(th2);
        float sn = sinf(th), cs = cosf(th);
        A = sn/th; Bc = (1.0f - cs)/th2; Cc = (th - sn)/(th2*th);
    }
    float K[3][3] = {{0,-wz,wy},{wz,0,-wx},{-wy,wx,0}};
    float K2[3][3];
    #pragma unroll
    for (int i = 0; i < 3; i++)
        #pragma unroll
        for (int j = 0; j < 3; j++)
            K2[i][j] = K[i][0]*K[0][j] + K[i][1]*K[1][j] + K[i][2]*K[2][j];
    float Re[3][3], Ve[3][3];
    #pragma unroll
    for (int i = 0; i < 3; i++)
        #pragma unroll
        for (int j = 0; j < 3; j++) {
            float id = (i == j) ? 1.0f : 0.0f;
            Re[i][j] = id + A*K[i][j] + Bc*K2[i][j];
            Ve[i][j] = id + Bc*K[i][j] + Cc*K2[i][j];
        }
    float te[3];
    te[0] = Ve[0][0]*vx + Ve[0][1]*vy + Ve[0][2]*vz;
    te[1] = Ve[1][0]*vx + Ve[1][1]*vy + Ve[1][2]*vz;
    te[2] = Ve[2][0]*vx + Ve[2][1]*vy + Ve[2][2]*vz;

    float* Pp = g_pose + b*16;
    float Pd[4][4];
    #pragma unroll
    for (int i = 0; i < 4; i++)
        #pragma unroll
        for (int j = 0; j < 4; j++) Pd[i][j] = Pp[i*4+j];
    #pragma unroll
    for (int j = 0; j < 4; j++) {
        float n0 = Re[0][0]*Pd[0][j] + Re[0][1]*Pd[1][j] + Re[0][2]*Pd[2][j] + te[0]*Pd[3][j];
        float n1 = Re[1][0]*Pd[0][j] + Re[1][1]*Pd[1][j] + Re[1][2]*Pd[2][j] + te[1]*Pd[3][j];
        float n2 = Re[2][0]*Pd[0][j] + Re[2][1]*Pd[1][j] + Re[2][2]*Pd[2][j] + te[2]*Pd[3][j];
        Pp[0*4+j] = n0; out[b*16 + 0*4 + j] = n0;
        Pp[1*4+j] = n1; out[b*16 + 1*4 + j] = n1;
        Pp[2*4+j] = n2; out[b*16 + 2*4 + j] = n2;
        out[b*16 + 3*4 + j] = Pd[3][j];
    }
}

// ---------------------------------------------------------------------------
extern "C" void kernel_launch(void* const* d_in, const int* in_sizes, int n_in,
                              void* d_out, int out_size)
{
    const float* pose   = (const float*)d_in[0];
    const float* I0     = (const float*)d_in[1];
    const float* I1     = (const float*)d_in[2];
    const float* intr   = (const float*)d_in[5];
    const float* depth0 = (const float*)d_in[6];
    const float* depth1 = (const float*)d_in[7];
    float* out = (float*)d_out;

    precompute_kernel<<<(BB*HWP + 255)/256, 256>>>(pose, I0, I1, depth0, depth1, intr);
    for (int it = 0; it < 3; it++) {
        reduce_kernel<<<dim3(NPB, BB), 128>>>(intr);
        solve_kernel<<<BB, 256>>>(out);
    }
}

// round 9
// speedup vs baseline: 1.3986x; 1.3986x over previous
#include <cuda_runtime.h>
#include <cuda_fp16.h>
#include <math.h>

#define BB 4
#define CC 8
#define HH 192
#define WW 256
#define HWP (HH*WW)
#define CHW (CC*HWP)
#define NPB 192            // blocks per batch (128 thr x 2 px = 256 px/block)
#define GW 0.01f

// packed pixel-major scratch (built once per launch)
__device__ __align__(16) __half g_I0h[(size_t)BB*HWP*8];   // [b][i][c]
__device__ __align__(16) __half g_I1h[(size_t)BB*HWP*8];   // [b][i][c]
__device__ __align__(16) __half g_Gh [(size_t)BB*HWP*16];  // [b][i][(gx,gy) per c]
__device__ __align__(8) __half g_Nh[(size_t)BB*HWP*4];     // normal half4
__device__ float  g_d0[(size_t)BB*HWP];                    // depth0 (V reconstructed)
__device__ float  g_d1[(size_t)BB*HWP];
__device__ float  g_pose[BB*16];
__device__ double g_part[(size_t)BB*NPB*27];

// ---------------------------------------------------------------------------
__global__ void precompute_kernel(const float* __restrict__ pose,
                                  const float* __restrict__ I0,
                                  const float* __restrict__ I1,
                                  const float* __restrict__ depth0,
                                  const float* __restrict__ depth1,
                                  const float* __restrict__ intr)
{
    int p = blockIdx.x * blockDim.x + threadIdx.x;
    if (p < BB*16) g_pose[p] = pose[p];
    if (p >= BB*HWP) return;
    int b = p / HWP;
    int i = p - b*HWP;
    int h = i / WW, w = i - h*WW;
    float fx = intr[b*4+0], fy = intr[b*4+1], cx = intr[b*4+2], cy = intr[b*4+3];
    int wl = max(w-1, 0), wr = min(w+1, WW-1);
    int hu = max(h-1, 0), hd = min(h+1, HH-1);

    const float* d0 = depth0 + b*HWP;
    float dc = d0[i];
    g_d0[p] = dc;
    g_d1[p] = depth1[p];

    float dl = d0[h*WW+wl], dr = d0[h*WW+wr];
    float du_ = d0[hu*WW+w], dd = d0[hd*WW+w];
    float pxc = ((float)w - cx)/fx, pyc = ((float)h - cy)/fy;
    float pxl = ((float)wl - cx)/fx, pxr = ((float)wr - cx)/fx;
    float pyu = ((float)hu - cy)/fy, pyd = ((float)hd - cy)/fy;
    float dx0 = 0.5f*(pxr*dr - pxl*dl);
    float dx1 = 0.5f*(pyc*dr - pyc*dl);
    float dx2 = 0.5f*(dr - dl);
    float dy0 = 0.5f*(pxc*dd - pxc*du_);
    float dy1 = 0.5f*(pyd*dd - pyu*du_);
    float dy2 = 0.5f*(dd - du_);
    float nx = dx1*dy2 - dx2*dy1;
    float ny = dx2*dy0 - dx0*dy2;
    float nz = dx0*dy1 - dx1*dy0;
    float inv = 1.0f / sqrtf(nx*nx + ny*ny + nz*nz + 1e-12f);
    {
        __half2 n01 = __floats2half2_rn(nx*inv, ny*inv);
        __half2 n23 = __floats2half2_rn(nz*inv, 0.f);
        uint2 nq;
        nq.x = *(unsigned*)&n01;
        nq.y = *(unsigned*)&n23;
        *(uint2*)(g_Nh + (size_t)p*4) = nq;
    }

    float i0v[8], i1v[8], gxy[16];
    #pragma unroll
    for (int c = 0; c < CC; c++) {
        const float* F = I0 + b*CHW + c*HWP;
        i0v[c] = F[i];
        i1v[c] = I1[b*CHW + c*HWP + i];
        gxy[2*c  ] = 0.5f*(F[h*WW+wr] - F[h*WW+wl]);
        gxy[2*c+1] = 0.5f*(F[hd*WW+w] - F[hu*WW+w]);
    }
    uint4 q;
    __half2 hh;
    #define PACKH(dst, src) \
        hh = __floats2half2_rn(src[0], src[1]); q.x = *(unsigned*)&hh; \
        hh = __floats2half2_rn(src[2], src[3]); q.y = *(unsigned*)&hh; \
        hh = __floats2half2_rn(src[4], src[5]); q.z = *(unsigned*)&hh; \
        hh = __floats2half2_rn(src[6], src[7]); q.w = *(unsigned*)&hh; \
        *(uint4*)(dst) = q;
    PACKH(g_I0h + (size_t)p*8, i0v)
    PACKH(g_I1h + (size_t)p*8, i1v)
    PACKH(g_Gh  + (size_t)p*16, gxy)
    PACKH(g_Gh  + (size_t)p*16 + 8, (gxy+8))
    #undef PACKH
}

// ---------------------------------------------------------------------------
__global__ __launch_bounds__(128, 6) void reduce_kernel(const float* __restrict__ intr)
{
    int b = blockIdx.y;
    float fx = intr[b*4+0], fy = intr[b*4+1], cx = intr[b*4+2], cy = intr[b*4+3];
    float rfx = 1.f/fx, rfy = 1.f/fy;
    const float* P = g_pose + b*16;
    float R00=P[0], R01=P[1], R02=P[2],  t0=P[3];
    float R10=P[4], R11=P[5], R12=P[6],  t1=P[7];
    float R20=P[8], R21=P[9], R22=P[10], t2=P[11];

    float vals[27];
    #pragma unroll
    for (int k = 0; k < 27; k++) vals[k] = 0.f;

    int ibase = blockIdx.x*256 + threadIdx.x;

    // ---- stage 1: both pixels' headers (overlapped dependent chains) ----
    float d1A = g_d1[(size_t)b*HWP + ibase];
    float d1B = g_d1[(size_t)b*HWP + ibase + 128];

    float wsP[2][4];
    int   o00P[2];
    float XxP[2], XyP[2], XzP[2], d1P[2];

    #pragma unroll
    for (int pp = 0; pp < 2; pp++) {
        int i = ibase + pp*128;
        float d1 = (pp == 0) ? d1A : d1B;
        int h = i >> 8, w = i & 255;           // WW = 256
        float px = ((float)w - cx)*rfx, py = ((float)h - cy)*rfy;
        float v1x = px*d1, v1y = py*d1;
        float Xx = R00*v1x + R01*v1y + R02*d1 + t0;
        float Xy = R10*v1x + R11*v1y + R12*d1 + t1;
        float Xz = R20*v1x + R21*v1y + R22*d1 + t2;
        bool valid = (Xz > 1e-8f);
        float zs = valid ? Xz : 1.f;
        float iz = __fdividef(1.f, zs);
        float u = fx*Xx*iz + cx;
        float v = fy*Xy*iz + cy;
        valid = valid & (u > 0.f) & (u < (float)(WW-1)) & (v > 0.f) & (v < (float)(HH-1));
        float u0f = floorf(u), v0f = floorf(v);
        float du = u - u0f, dv = v - v0f;
        float m = valid ? 1.f : 0.f;
        wsP[pp][0] = m*(1.f-du)*(1.f-dv);
        wsP[pp][1] = m*du*(1.f-dv);
        wsP[pp][2] = m*(1.f-du)*dv;
        wsP[pp][3] = m*du*dv;
        o00P[pp] = valid ? ((int)v0f*WW + (int)u0f) : 0;
        XxP[pp]=Xx; XyP[pp]=Xy; XzP[pp]=zs; d1P[pp]=d1;
    }

    // ---- stage 2: taps + accumulate per pixel (branch-free) ----
    #pragma unroll
    for (int pp = 0; pp < 2; pp++) {
        int i = ibase + pp*128;
        int o00 = o00P[pp];
        int offs[4] = { o00, o00+1, o00+WW, o00+WW+1 };
        float Xx=XxP[pp], Xy=XyP[pp], Xz=XzP[pp];
        float d1 = d1P[pp];
        float v1x = (((float)(i & 255)) - cx)*rfx*d1;
        float v1y = (((float)(i >> 8))  - cy)*rfy*d1;
        float v1z = d1;

        __half2 i0a[4], ga[8], na[2];
        __half2 hz = __float2half2_rn(0.f);
        #pragma unroll
        for (int c = 0; c < 4; c++) i0a[c] = hz;
        #pragma unroll
        for (int c = 0; c < 8; c++) ga[c] = hz;
        na[0] = hz; na[1] = hz;
        float S=0.f, Sx=0.f, Sy=0.f;   // depth0 tap sums for V reconstruction

        #pragma unroll
        for (int t = 0; t < 4; t++) {
            size_t base = (size_t)b*HWP + offs[t];
            float wtf = wsP[pp][t];
            __half2 wt2 = __float2half2_rn(wtf);
            uint4 qI = *(const uint4*)(g_I0h + base*8);
            i0a[0] = __hfma2(wt2, *(__half2*)&qI.x, i0a[0]);
            i0a[1] = __hfma2(wt2, *(__half2*)&qI.y, i0a[1]);
            i0a[2] = __hfma2(wt2, *(__half2*)&qI.z, i0a[2]);
            i0a[3] = __hfma2(wt2, *(__half2*)&qI.w, i0a[3]);
            uint4 qG0 = *(const uint4*)(g_Gh + base*16);
            uint4 qG1 = *(const uint4*)(g_Gh + base*16 + 8);
            ga[0] = __hfma2(wt2, *(__half2*)&qG0.x, ga[0]);
            ga[1] = __hfma2(wt2, *(__half2*)&qG0.y, ga[1]);
            ga[2] = __hfma2(wt2, *(__half2*)&qG0.z, ga[2]);
            ga[3] = __hfma2(wt2, *(__half2*)&qG0.w, ga[3]);
            ga[4] = __hfma2(wt2, *(__half2*)&qG1.x, ga[4]);
            ga[5] = __hfma2(wt2, *(__half2*)&qG1.y, ga[5]);
            ga[6] = __hfma2(wt2, *(__half2*)&qG1.z, ga[6]);
            ga[7] = __hfma2(wt2, *(__half2*)&qG1.w, ga[7]);
            uint2 nq = *(const uint2*)(g_Nh + base*4);
            na[0] = __hfma2(wt2, *(__half2*)&nq.x, na[0]);
            na[1] = __hfma2(wt2, *(__half2*)&nq.y, na[1]);
            float dt = g_d0[base];
            float wd = wtf*dt;
            S += wd;
            if (t == 1 || t == 3) Sx += wd;   // right column (u0+1)
            if (t == 2 || t == 3) Sy += wd;   // bottom row  (v0+1)
        }
        float2 nf01 = __half22float2(na[0]);
        float2 nf2  = __half22float2(na[1]);
        float Nw0 = nf01.x, Nw1 = nf01.y, Nw2 = nf2.x;
        // reconstruct bilinear V0: rV = ( rfx*((u0-cx)S + Sx), rfy*((v0-cy)S + Sy), S )
        float u0c = (float)(o00 & 255) - cx;
        float v0c = (float)(o00 >> 8)  - cy;
        float rVx = rfx*(u0c*S + Sx);
        float rVy = rfy*(v0c*S + Sy);

        float invz = __fdividef(1.f, Xz);
        float a0 = fx*invz, a2 = -fx*Xx*invz*invz;
        float b1 = fy*invz, b2 = -fy*Xy*invz*invz;
        float Jw0[6] = { a2*Xy, a0*Xz - a2*Xx, -a0*Xy, a0, 0.f, a2 };
        float Jw1[6] = { b2*Xy - b1*Xz, -b2*Xx, b1*Xx, 0.f, b1, b2 };

        // photometric factored scalars (zero when invalid: all taps zero)
        float aS=0.f, bS=0.f, cS=0.f, rxS=0.f, ryS=0.f;
        {
            const uint4 qI1 = *(const uint4*)(g_I1h + ((size_t)b*HWP + i)*8);
            const __half2* I1h2 = (const __half2*)&qI1;
            #pragma unroll
            for (int c2 = 0; c2 < 4; c2++) {
                float2 i1f = __half22float2(I1h2[c2]);
                float2 i0f = __half22float2(i0a[c2]);
                float2 g0f = __half22float2(ga[2*c2]);
                float2 g1f = __half22float2(ga[2*c2+1]);
                float rA = i1f.x - i0f.x;
                float rB = i1f.y - i0f.y;
                float wtA = fminf(1.f, __fdividef(0.5f, fabsf(rA)));
                float wtB = fminf(1.f, __fdividef(0.5f, fabsf(rB)));
                aS  += wtA*g0f.x*g0f.x;  bS  += wtA*g0f.x*g0f.y;  cS  += wtA*g0f.y*g0f.y;
                float wrA = wtA*rA;
                rxS += g0f.x*wrA;        ryS += g0f.y*wrA;
                aS  += wtB*g1f.x*g1f.x;  bS  += wtB*g1f.x*g1f.y;  cS  += wtB*g1f.y*g1f.y;
                float wrB = wtB*rB;
                rxS += g1f.x*wrB;        ryS += g1f.y*wrB;
            }
        }

        // ICP point-to-plane row (Nw=S=0 when invalid -> q=0 -> Jz=0)
        float dfx = Xx - rVx, dfy = Xy - rVy, dfz = Xz - S;
        float d2 = dfx*dfx + dfy*dfy + dfz*dfz;
        float q0 = Nw0*R00 + Nw1*R10 + Nw2*R20;
        float q1 = Nw0*R01 + Nw1*R11 + Nw2*R21;
        float q2 = Nw0*R02 + Nw1*R12 + Nw2*R22;
        float Jr0 = q1*v1z - q2*v1y;
        float Jr1 = q2*v1x - q0*v1z;
        float Jr2 = q0*v1y - q1*v1x;
        float sd01 = (d1 / 525.0f) * 5.5f;
        float sd2  = d1*d1*0.4f / (525.0f*1.2f);
        float cov = (q0*q0 + q1*q1)*sd01*sd01 + q2*q2*sd2*sd2;
        float sinv = __frsqrt_rn(cov + 1e-8f);
        float res = (Nw0*dfx + Nw1*dfy + Nw2*dfz) * sinv;
        if (d2 + 1e-12f > 0.01f) res = 1e-6f;
        float Jz[6] = { -Jr0*sinv*GW, -Jr1*sinv*GW, -Jr2*sinv*GW,
                         q0*sinv*GW,   q1*sinv*GW,   q2*sinv*GW };
        float rz = -GW * res;
        float wz = fminf(1.f, __fdividef(0.5f, fabsf(rz)));
        float wrz = wz * rz;

        float Ai[6], Bi[6], Wi[6];
        #pragma unroll
        for (int ii = 0; ii < 6; ii++) {
            Ai[ii] = aS*Jw0[ii] + bS*Jw1[ii];
            Bi[ii] = bS*Jw0[ii] + cS*Jw1[ii];
            Wi[ii] = wz*Jz[ii];
        }
        int k = 0;
        #pragma unroll
        for (int ii = 0; ii < 6; ii++) {
            #pragma unroll
            for (int jj = ii; jj < 6; jj++)
                vals[k++] += Ai[ii]*Jw0[jj] + Bi[ii]*Jw1[jj] + Wi[ii]*Jz[jj];
            vals[21+ii] += rxS*Jw0[ii] + ryS*Jw1[ii] + Jz[ii]*wrz;
        }
    }

    // block reduction: per-column fp32 warp shuffle tree, fp64 across 4 warps
    __shared__ float sw[4][27];
    int lane = threadIdx.x & 31, wid = threadIdx.x >> 5;
    #pragma unroll
    for (int k = 0; k < 27; k++) {
        float val = vals[k];
        #pragma unroll
        for (int off = 16; off > 0; off >>= 1)
            val += __shfl_down_sync(0xffffffffu, val, off);
        if (lane == 0) sw[wid][k] = val;
    }
    __syncthreads();
    if (threadIdx.x < 27) {
        double s = 0.0;
        #pragma unroll
        for (int w2 = 0; w2 < 4; w2++) s += (double)sw[w2][threadIdx.x];
        g_part[((size_t)b*NPB + blockIdx.x)*27 + threadIdx.x] = s;
    }
}

// ---------------------------------------------------------------------------
__global__ void solve_kernel(float* __restrict__ out)
{
    int b = blockIdx.x;
    __shared__ float sv[27];
    int t = threadIdx.x;
    int g = t >> 3, l = t & 7;
    bool live = (g < 27);
    double s = 0.0;
    if (live) {
        #pragma unroll 4
        for (int k = l; k < NPB; k += 8)
            s += g_part[((size_t)b*NPB + k)*27 + g];
    }
    #pragma unroll
    for (int off = 4; off > 0; off >>= 1)
        s += __shfl_down_sync(0xffffffffu, s, off, 8);
    if (live && l == 0) sv[g] = (float)s;
    __syncthreads();
    if (t != 0) return;

    float Hm[6][7];
    {
        int k = 0;
        for (int i = 0; i < 6; i++)
            for (int j = i; j < 6; j++) { Hm[i][j] = sv[k]; Hm[j][i] = sv[k]; k++; }
        for (int i = 0; i < 6; i++) Hm[i][i] += 1e-6f;
        for (int i = 0; i < 6; i++) Hm[i][6] = sv[21 + i];
    }
    #pragma unroll
    for (int col = 0; col < 6; col++) {
        int piv = col; float mx = fabsf(Hm[col][col]);
        #pragma unroll
        for (int r = col+1; r < 6; r++)
            if (fabsf(Hm[r][col]) > mx) { mx = fabsf(Hm[r][col]); piv = r; }
        if (piv != col)
            #pragma unroll
            for (int c = 0; c < 7; c++) { float tmp = Hm[col][c]; Hm[col][c] = Hm[piv][c]; Hm[piv][c] = tmp; }
        float inv = 1.0f / Hm[col][col];
        #pragma unroll
        for (int r = col+1; r < 6; r++) {
            float f = Hm[r][col] * inv;
            #pragma unroll
            for (int c = col; c < 7; c++) Hm[r][c] -= f * Hm[col][c];
        }
    }
    float xi[6];
    #pragma unroll
    for (int r = 5; r >= 0; r--) {
        float s2 = Hm[r][6];
        #pragma unroll
        for (int c = r+1; c < 6; c++) s2 -= Hm[r][c] * xi[c];
        xi[r] = s2 / Hm[r][r];
    }
    float wx = xi[0], wy = xi[1], wz = xi[2], vx = xi[3], vy = xi[4], vz = xi[5];
    float th2 = wx*wx + wy*wy + wz*wz;
    float A, Bc, Cc;
    if (th2 < 1e-8f) { A = 1.0f - th2/6.0f; Bc = 0.5f - th2/24.0f; Cc = 1.0f/6.0f - th2/120.0f; }
    else {
        float th = sqrtf(th2);
        float sn = sinf(th), cs = cosf(th);
        A = sn/th; Bc = (1.0f - cs)/th2; Cc = (th - sn)/(th2*th);
    }
    float K[3][3] = {{0,-wz,wy},{wz,0,-wx},{-wy,wx,0}};
    float K2[3][3];
    #pragma unroll
    for (int i = 0; i < 3; i++)
        #pragma unroll
        for (int j = 0; j < 3; j++)
            K2[i][j] = K[i][0]*K[0][j] + K[i][1]*K[1][j] + K[i][2]*K[2][j];
    float Re[3][3], Ve[3][3];
    #pragma unroll
    for (int i = 0; i < 3; i++)
        #pragma unroll
        for (int j = 0; j < 3; j++) {
            float id = (i == j) ? 1.0f : 0.0f;
            Re[i][j] = id + A*K[i][j] + Bc*K2[i][j];
            Ve[i][j] = id + Bc*K[i][j] + Cc*K2[i][j];
        }
    float te[3];
    te[0] = Ve[0][0]*vx + Ve[0][1]*vy + Ve[0][2]*vz;
    te[1] = Ve[1][0]*vx + Ve[1][1]*vy + Ve[1][2]*vz;
    te[2] = Ve[2][0]*vx + Ve[2][1]*vy + Ve[2][2]*vz;

    float* Pp = g_pose + b*16;
    float Pd[4][4];
    #pragma unroll
    for (int i = 0; i < 4; i++)
        #pragma unroll
        for (int j = 0; j < 4; j++) Pd[i][j] = Pp[i*4+j];
    #pragma unroll
    for (int j = 0; j < 4; j++) {
        float n0 = Re[0][0]*Pd[0][j] + Re[0][1]*Pd[1][j] + Re[0][2]*Pd[2][j] + te[0]*Pd[3][j];
        float n1 = Re[1][0]*Pd[0][j] + Re[1][1]*Pd[1][j] + Re[1][2]*Pd[2][j] + te[1]*Pd[3][j];
        float n2 = Re[2][0]*Pd[0][j] + Re[2][1]*Pd[1][j] + Re[2][2]*Pd[2][j] + te[2]*Pd[3][j];
        Pp[0*4+j] = n0; out[b*16 + 0*4 + j] = n0;
        Pp[1*4+j] = n1; out[b*16 + 1*4 + j] = n1;
        Pp[2*4+j] = n2; out[b*16 + 2*4 + j] = n2;
        out[b*16 + 3*4 + j] = Pd[3][j];
    }
}

// ---------------------------------------------------------------------------
extern "C" void kernel_launch(void* const* d_in, const int* in_sizes, int n_in,
                              void* d_out, int out_size)
{
    const float* pose   = (const float*)d_in[0];
    const float* I0     = (const float*)d_in[1];
    const float* I1     = (const float*)d_in[2];
    const float* intr   = (const float*)d_in[5];
    const float* depth0 = (const float*)d_in[6];
    const float* depth1 = (const float*)d_in[7];
    float* out = (float*)d_out;

    precompute_kernel<<<(BB*HWP + 255)/256, 256>>>(pose, I0, I1, depth0, depth1, intr);
    for (int it = 0; it < 3; it++) {
        reduce_kernel<<<dim3(NPB, BB), 128>>>(intr);
        solve_kernel<<<BB, 256>>>(out);
    }
}